// round 4
// baseline (speedup 1.0000x reference)
#include <cuda_runtime.h>
#include <cuda_fp16.h>
#include <math.h>
#include <stdint.h>

#define N_LEVELS 16
#define HASH_MASK 32767u
#define HASHMAP_SIZE 32768
#define PTS_PER_CTA 54272      // 37 ranges * 16 levels = 592 CTAs = exactly 4 waves
#define CTA_THREADS 1024
#define MAX_POINTS 2000000

#define TP_THREADS 256
#define TP_PTS 512

struct ResArr { int r[N_LEVELS]; };

// fp16x2 copy of tables, pre-scaled by 2^14 (values ~uniform(±1e-4) -> ±1.64)
__device__ __half2 g_tbl_h[N_LEVELS * HASHMAP_SIZE];
// level-major scratch: g_scratch[l*n + p], 2M*16*8B = 256 MB
__device__ float2 g_scratch[(size_t)MAX_POINTS * N_LEVELS];

__global__ void __launch_bounds__(256)
cvt_tables_kernel(const float* __restrict__ tables)
{
    int i = blockIdx.x * blockDim.x + threadIdx.x;
    if (i < N_LEVELS * HASHMAP_SIZE) {
        float2 f = ((const float2*)tables)[i];
        g_tbl_h[i] = __floats2half2_rn(f.x * 16384.0f, f.y * 16384.0f);
    }
}

__global__ void __launch_bounds__(CTA_THREADS)
hash_enc4d_smem_kernel(const float* __restrict__ coords,
                       const float* __restrict__ ts,
                       ResArr res, int n)
{
    extern __shared__ __half2 s_tbl[];  // 32768 entries = 128 KB

    const int l = blockIdx.x;  // level fastest-varying: co-resident levels share coords in L2

    // Cooperative table load: 128 KB = 8192 int4
    {
        const int4* __restrict__ src = (const int4*)(g_tbl_h + (size_t)l * HASHMAP_SIZE);
        int4* dst = (int4*)s_tbl;
#pragma unroll
        for (int i = threadIdx.x; i < 8192; i += CTA_THREADS)
            dst[i] = src[i];
    }
    __syncthreads();

    const float rf = (float)res.r[l];
    const uint32_t P1 = 2654435761u, P2 = 805459861u, P3 = 3674653429u;
    float2* __restrict__ sc = g_scratch + (size_t)l * n;

    const int base = blockIdx.y * PTS_PER_CTA;
    const int end = min(base + PTS_PER_CTA, n);

    for (int p = base + threadIdx.x; p < end; p += CTA_THREADS) {
        float x = (coords[3 * p + 0] + 50.0f) / 100.0f;
        float y = (coords[3 * p + 1] + 50.0f) / 100.0f;
        float z = (coords[3 * p + 2] + 50.0f) / 100.0f;
        float t = ts[p];
        t = fminf(fmaxf(t, 0.0f), 1.0f);

        float sx = x * rf, sy = y * rf, sz = z * rf, st = t * rf;
        float gxf = floorf(sx), gyf = floorf(sy), gzf = floorf(sz), gtf = floorf(st);
        float fx = sx - gxf, fy = sy - gyf, fz = sz - gzf, ft = st - gtf;

        uint32_t gx = (uint32_t)(int)gxf;
        uint32_t gy = (uint32_t)(int)gyf;
        uint32_t gz = (uint32_t)(int)gzf;
        uint32_t gt = (uint32_t)(int)gtf;

        uint32_t tx0 = gx,      tx1 = gx + 1u;
        uint32_t ty0 = gy * P1, ty1 = ty0 + P1;
        uint32_t tz0 = gz * P2, tz1 = tz0 + P2;
        uint32_t tt0 = gt * P3, tt1 = tt0 + P3;

        uint32_t hxy[4], hzt[4];
        hxy[0] = tx0 ^ ty0; hxy[1] = tx1 ^ ty0;
        hxy[2] = tx0 ^ ty1; hxy[3] = tx1 ^ ty1;
        hzt[0] = tz0 ^ tt0; hzt[1] = tz1 ^ tt0;
        hzt[2] = tz0 ^ tt1; hzt[3] = tz1 ^ tt1;

        float ux = 1.0f - fx, uy = 1.0f - fy, uz = 1.0f - fz, ut = 1.0f - ft;
        float wxy[4], wzt[4];
        wxy[0] = ux * uy; wxy[1] = fx * uy; wxy[2] = ux * fy; wxy[3] = fx * fy;
        wzt[0] = uz * ut; wzt[1] = fz * ut; wzt[2] = uz * ft; wzt[3] = fz * ft;

        float a0 = 0.0f, a1 = 0.0f;
#pragma unroll
        for (int j = 0; j < 4; ++j) {
#pragma unroll
            for (int i = 0; i < 4; ++i) {
                uint32_t idx = (hxy[i] ^ hzt[j]) & HASH_MASK;
                float2 f = __half22float2(s_tbl[idx]);
                float w = wxy[i] * wzt[j];
                a0 = fmaf(w, f.x, a0);
                a1 = fmaf(w, f.y, a1);
            }
        }
        // level-major coalesced store (2 wavefronts/warp instead of 32)
        sc[p] = make_float2(a0 * 0x1p-14f, a1 * 0x1p-14f);
    }
}

// Transpose scratch[l][p] -> out[p][l], smem-tiled, coalesced both sides.
__global__ void __launch_bounds__(TP_THREADS)
transpose_kernel(float* __restrict__ out, int n)
{
    // tile rows = points, 16 float2 + 1 float4 pad -> row = 18 float2 = 144 B (f4-aligned)
    extern __shared__ float2 tile[];  // TP_PTS * 18 float2 = 73728 B

    const int base = blockIdx.x * TP_PTS;

    // Phase 1: read level-major (coalesced), scatter into tile rows
#pragma unroll
    for (int l = 0; l < N_LEVELS; ++l) {
        const float2* __restrict__ sc = g_scratch + (size_t)l * n;
        for (int i = threadIdx.x; i < TP_PTS; i += TP_THREADS) {
            int p = base + i;
            if (p < n) tile[i * 18 + l] = sc[p];
        }
    }
    __syncthreads();

    // Phase 2: write point-major rows, fully coalesced float4
    float4* __restrict__ out4 = (float4*)out;
    for (int idx = threadIdx.x; idx < TP_PTS * 8; idx += TP_THREADS) {
        int pt = idx >> 3;
        int q  = idx & 7;
        int p  = base + pt;
        if (p < n)
            out4[(size_t)p * 8 + q] = ((const float4*)(tile + pt * 18))[q];
    }
}

extern "C" void kernel_launch(void* const* d_in, const int* in_sizes, int n_in,
                              void* d_out, int out_size)
{
    const float* coords = (const float*)d_in[0];
    const float* ts     = (const float*)d_in[1];
    const float* tables = (const float*)d_in[2];
    float* out          = (float*)d_out;

    int n = in_sizes[0] / 3;

    ResArr ra;
    for (int l = 0; l < N_LEVELS; ++l) {
        double f = (double)l / 15.0;
        double v = exp(log(16.0) * (1.0 - f) + log(512.0) * f);
        ra.r[l] = (int)v;
    }

    const int smem_main = HASHMAP_SIZE * (int)sizeof(__half2);  // 131072
    const int smem_tp   = TP_PTS * 18 * (int)sizeof(float2);    // 73728
    static int configured = 0;
    if (!configured) {
        cudaFuncSetAttribute(hash_enc4d_smem_kernel,
                             cudaFuncAttributeMaxDynamicSharedMemorySize, smem_main);
        cudaFuncSetAttribute(transpose_kernel,
                             cudaFuncAttributeMaxDynamicSharedMemorySize, smem_tp);
        configured = 1;
    }

    // 1) convert tables to pre-scaled half2
    {
        int total = N_LEVELS * HASHMAP_SIZE;
        cvt_tables_kernel<<<(total + 255) / 256, 256>>>(tables);
    }

    // 2) level-fastest smem-gather encode -> level-major scratch
    dim3 grid(N_LEVELS, (n + PTS_PER_CTA - 1) / PTS_PER_CTA);
    hash_enc4d_smem_kernel<<<grid, CTA_THREADS, smem_main>>>(coords, ts, ra, n);

    // 3) transpose scratch -> point-major output
    int tp_blocks = (n + TP_PTS - 1) / TP_PTS;
    transpose_kernel<<<tp_blocks, TP_THREADS, smem_tp>>>(out, n);
}

// round 5
// speedup vs baseline: 1.3188x; 1.3188x over previous
#include <cuda_runtime.h>
#include <cuda_fp16.h>
#include <math.h>
#include <stdint.h>

#define N_LEVELS 16
#define HASH_MASK 32767u
#define HASHMAP_SIZE 32768
#define PTS_PER_CTA 54272      // 37 ranges * 16 levels = 592 CTAs = exactly 4 waves
#define CTA_THREADS 1024
#define MAX_POINTS 2000000

#define TP_THREADS 256
#define TP_PTS 512
#define TP_STRIDE 17           // half2 units; odd -> conflict-free STS

struct ResArr { int r[N_LEVELS]; };

// fp16x2 copy of tables, pre-scaled by 2^14 (values ~uniform(±1e-4) -> ±1.64)
__device__ __half2 g_tbl_h[N_LEVELS * HASHMAP_SIZE];
// level-major half2 scratch (still carrying the 2^14 prescale): 128 MB
__device__ __half2 g_scr[(size_t)MAX_POINTS * N_LEVELS];

__global__ void __launch_bounds__(256)
cvt_tables_kernel(const float* __restrict__ tables)
{
    int i = blockIdx.x * blockDim.x + threadIdx.x;
    if (i < N_LEVELS * HASHMAP_SIZE) {
        float2 f = ((const float2*)tables)[i];
        g_tbl_h[i] = __floats2half2_rn(f.x * 16384.0f, f.y * 16384.0f);
    }
}

__global__ void __launch_bounds__(CTA_THREADS)
hash_enc4d_smem_kernel(const float* __restrict__ coords,
                       const float* __restrict__ ts,
                       ResArr res, int n)
{
    extern __shared__ __half2 s_tbl[];  // 32768 entries = 128 KB

    const int l = blockIdx.x;  // level fastest-varying: co-resident levels share coords in L2

    // Cooperative table load: 128 KB = 8192 int4
    {
        const int4* __restrict__ src = (const int4*)(g_tbl_h + (size_t)l * HASHMAP_SIZE);
        int4* dst = (int4*)s_tbl;
#pragma unroll
        for (int i = threadIdx.x; i < 8192; i += CTA_THREADS)
            dst[i] = src[i];
    }
    __syncthreads();

    const float rf = (float)res.r[l];
    const uint32_t P1 = 2654435761u, P2 = 805459861u, P3 = 3674653429u;
    __half2* __restrict__ sc = g_scr + (size_t)l * n;

    const int base = blockIdx.y * PTS_PER_CTA;
    const int end = min(base + PTS_PER_CTA, n);

    for (int p = base + threadIdx.x; p < end; p += CTA_THREADS) {
        float x = (coords[3 * p + 0] + 50.0f) / 100.0f;
        float y = (coords[3 * p + 1] + 50.0f) / 100.0f;
        float z = (coords[3 * p + 2] + 50.0f) / 100.0f;
        float t = ts[p];
        t = fminf(fmaxf(t, 0.0f), 1.0f);

        float sx = x * rf, sy = y * rf, sz = z * rf, st = t * rf;
        float gxf = floorf(sx), gyf = floorf(sy), gzf = floorf(sz), gtf = floorf(st);
        float fx = sx - gxf, fy = sy - gyf, fz = sz - gzf, ft = st - gtf;

        uint32_t gx = (uint32_t)(int)gxf;
        uint32_t gy = (uint32_t)(int)gyf;
        uint32_t gz = (uint32_t)(int)gzf;
        uint32_t gt = (uint32_t)(int)gtf;

        uint32_t tx0 = gx,      tx1 = gx + 1u;
        uint32_t ty0 = gy * P1, ty1 = ty0 + P1;
        uint32_t tz0 = gz * P2, tz1 = tz0 + P2;
        uint32_t tt0 = gt * P3, tt1 = tt0 + P3;

        uint32_t hxy[4], hzt[4];
        hxy[0] = tx0 ^ ty0; hxy[1] = tx1 ^ ty0;
        hxy[2] = tx0 ^ ty1; hxy[3] = tx1 ^ ty1;
        hzt[0] = tz0 ^ tt0; hzt[1] = tz1 ^ tt0;
        hzt[2] = tz0 ^ tt1; hzt[3] = tz1 ^ tt1;

        float ux = 1.0f - fx, uy = 1.0f - fy, uz = 1.0f - fz, ut = 1.0f - ft;
        float wxy[4], wzt[4];
        wxy[0] = ux * uy; wxy[1] = fx * uy; wxy[2] = ux * fy; wxy[3] = fx * fy;
        wzt[0] = uz * ut; wzt[1] = fz * ut; wzt[2] = uz * ft; wzt[3] = fz * ft;

        float a0 = 0.0f, a1 = 0.0f;
#pragma unroll
        for (int j = 0; j < 4; ++j) {
#pragma unroll
            for (int i = 0; i < 4; ++i) {
                uint32_t idx = (hxy[i] ^ hzt[j]) & HASH_MASK;
                float2 f = __half22float2(s_tbl[idx]);
                float w = wxy[i] * wzt[j];
                a0 = fmaf(w, f.x, a0);
                a1 = fmaf(w, f.y, a1);
            }
        }
        // coalesced half2 store, keeps the 2^14 prescale (values in fp16-normal range)
        sc[p] = __floats2half2_rn(a0, a1);
    }
}

// Transpose + descale: g_scr[l][p] (half2, prescaled) -> out[p][l] (float2).
// Tile 512 pts x 16 levels, row stride 17 half2 -> conflict-free STS, <=2-way LDS.
__global__ void __launch_bounds__(TP_THREADS)
transpose_kernel(float* __restrict__ out, int n)
{
    __shared__ __half2 tile[TP_PTS * TP_STRIDE];  // 512*17*4 = 34816 B

    const int base = blockIdx.x * TP_PTS;

    // Phase 1: read level-major (coalesced LDG.32), store to tile (conflict-free)
#pragma unroll
    for (int l = 0; l < N_LEVELS; ++l) {
        const __half2* __restrict__ sc = g_scr + (size_t)l * n;
#pragma unroll
        for (int i = threadIdx.x; i < TP_PTS; i += TP_THREADS) {
            int p = base + i;
            tile[i * TP_STRIDE + l] = (p < n) ? sc[p] : __half2half2(__float2half(0.0f));
        }
    }
    __syncthreads();

    // Phase 2: each thread emits one float4 (2 levels of one point), coalesced STG.128
    float4* __restrict__ out4 = (float4*)out;
#pragma unroll
    for (int k = 0; k < (TP_PTS * 8) / TP_THREADS; ++k) {
        int idx = threadIdx.x + k * TP_THREADS;
        int pt = idx >> 3;          // 0..511
        int q  = idx & 7;           // which float4 of the 128-B row
        int p  = base + pt;
        if (p < n) {
            __half2 h0 = tile[pt * TP_STRIDE + 2 * q];
            __half2 h1 = tile[pt * TP_STRIDE + 2 * q + 1];
            float2 f0 = __half22float2(h0);
            float2 f1 = __half22float2(h1);
            out4[(size_t)p * 8 + q] = make_float4(f0.x * 0x1p-14f, f0.y * 0x1p-14f,
                                                  f1.x * 0x1p-14f, f1.y * 0x1p-14f);
        }
    }
}

extern "C" void kernel_launch(void* const* d_in, const int* in_sizes, int n_in,
                              void* d_out, int out_size)
{
    const float* coords = (const float*)d_in[0];
    const float* ts     = (const float*)d_in[1];
    const float* tables = (const float*)d_in[2];
    float* out          = (float*)d_out;

    int n = in_sizes[0] / 3;

    ResArr ra;
    for (int l = 0; l < N_LEVELS; ++l) {
        double f = (double)l / 15.0;
        double v = exp(log(16.0) * (1.0 - f) + log(512.0) * f);
        ra.r[l] = (int)v;
    }

    const int smem_main = HASHMAP_SIZE * (int)sizeof(__half2);  // 131072
    static int configured = 0;
    if (!configured) {
        cudaFuncSetAttribute(hash_enc4d_smem_kernel,
                             cudaFuncAttributeMaxDynamicSharedMemorySize, smem_main);
        configured = 1;
    }

    // 1) convert tables to pre-scaled half2
    {
        int total = N_LEVELS * HASHMAP_SIZE;
        cvt_tables_kernel<<<(total + 255) / 256, 256>>>(tables);
    }

    // 2) level-fastest smem-gather encode -> half2 level-major scratch
    dim3 grid(N_LEVELS, (n + PTS_PER_CTA - 1) / PTS_PER_CTA);
    hash_enc4d_smem_kernel<<<grid, CTA_THREADS, smem_main>>>(coords, ts, ra, n);

    // 3) conflict-free transpose + descale -> point-major fp32 output
    int tp_blocks = (n + TP_PTS - 1) / TP_PTS;
    transpose_kernel<<<tp_blocks, TP_THREADS>>>(out, n);
}